// round 1
// baseline (speedup 1.0000x reference)
#include <cuda_runtime.h>
#include <math.h>

#define NN 30000
#define EE 510000      // 30000*16 + 30000 self loops
#define TT 2
#define KDIM 128       // F_IN == H1 == 128 (GEMM K for both layers)

// ---------------- scratch (device globals; no allocation allowed) ----------------
__device__ float  g_h[(size_t)NN * 256];     // GEMM output, max 2C = 256
__device__ float  g_mu0[(size_t)NN * 128];   // layer outputs / fused inputs
__device__ float  g_mu1[(size_t)NN * 128];
__device__ float  g_alpha[EE];
__device__ float  g_si[NN];
__device__ float  g_sj[NN];
__device__ float  g_invdeg[TT][NN];
__device__ int    g_deg[TT][NN];
__device__ int    g_rowptr[TT][NN + 1];
__device__ int    g_woff[TT][NN];
__device__ int    g_csrc[TT][EE];
__device__ int    g_cdst[TT][EE];
__device__ double g_acc[8];  // [0..3] ixz sums (L1t0,L1t1,L2t0,L2t1), [4..7] skl sums

// ---------------- helpers ----------------
__device__ __forceinline__ float blockReduceSum(float v, float* sm) {
    int lane = threadIdx.x & 31, wid = threadIdx.x >> 5;
#pragma unroll
    for (int o = 16; o; o >>= 1) v += __shfl_down_sync(0xffffffffu, v, o);
    if (lane == 0) sm[wid] = v;
    __syncthreads();
    int nw = (blockDim.x + 31) >> 5;
    v = (threadIdx.x < nw) ? sm[threadIdx.x] : 0.f;
    if (wid == 0) {
#pragma unroll
        for (int o = 16; o; o >>= 1) v += __shfl_down_sync(0xffffffffu, v, o);
    }
    return v;  // valid on thread 0
}

// ---------------- setup kernels ----------------
__global__ void zero_kernel() {
    int i = blockIdx.x * blockDim.x + threadIdx.x;
    if (i < TT * NN) (&g_deg[0][0])[i] = 0;
    if (i < 8) g_acc[i] = 0.0;
}

__global__ void hist_kernel(const int* __restrict__ dst, int t) {
    int e = blockIdx.x * blockDim.x + threadIdx.x;
    if (e < EE) atomicAdd(&g_deg[t][dst[e]], 1);
}

__global__ void scan_kernel(int t) {
    const int T = 1024;
    int tid = threadIdx.x;
    const int chunk = (NN + T - 1) / T;  // 30
    int s0 = tid * chunk;
    int sum = 0;
    for (int i = 0; i < chunk; i++) {
        int idx = s0 + i;
        if (idx < NN) sum += g_deg[t][idx];
    }
    int lane = tid & 31, wid = tid >> 5;
    int v = sum;
#pragma unroll
    for (int o = 1; o < 32; o <<= 1) {
        int u = __shfl_up_sync(0xffffffffu, v, o);
        if (lane >= o) v += u;
    }
    __shared__ int ws[32];
    if (lane == 31) ws[wid] = v;
    __syncthreads();
    if (wid == 0) {
        int w = ws[lane];
#pragma unroll
        for (int o = 1; o < 32; o <<= 1) {
            int u = __shfl_up_sync(0xffffffffu, w, o);
            if (lane >= o) w += u;
        }
        ws[lane] = w;
    }
    __syncthreads();
    int excl = (v - sum) + (wid > 0 ? ws[wid - 1] : 0);
    int run = excl;
    for (int i = 0; i < chunk; i++) {
        int idx = s0 + i;
        if (idx < NN) {
            int d = g_deg[t][idx];
            g_rowptr[t][idx] = run;
            g_woff[t][idx] = run;
            g_invdeg[t][idx] = 1.0f / (float)d;
            run += d;
        }
    }
    if (tid == T - 1) g_rowptr[t][NN] = run;
}

__global__ void scatter_kernel(const int* __restrict__ src, const int* __restrict__ dst, int t) {
    int e = blockIdx.x * blockDim.x + threadIdx.x;
    if (e < EE) {
        int d = dst[e];
        int pos = atomicAdd(&g_woff[t][d], 1);
        g_csrc[t][pos] = src[e];
        g_cdst[t][pos] = d;
    }
}

// ---------------- GEMM: C[M, Ncols] = A[M,128] * B[128, Ncols] ----------------
__global__ void gemm_kernel(const float* __restrict__ A, const float* __restrict__ B,
                            float* __restrict__ C, int M, int Ncols) {
    __shared__ float As[16][64];
    __shared__ float Bs[16][64];
    int tid = threadIdx.x;
    int tx = tid % 16, ty = tid / 16;
    int row0 = blockIdx.y * 64, col0 = blockIdx.x * 64;
    float acc[4][4] = {};
    int arow = tid / 4;          // 0..63
    int acol4 = (tid % 4) * 4;   // 0,4,8,12
    int brow = tid / 16;         // 0..15
    int bcol4 = (tid % 16) * 4;
    for (int k0 = 0; k0 < KDIM; k0 += 16) {
        float4 av = make_float4(0.f, 0.f, 0.f, 0.f);
        if (row0 + arow < M)
            av = *(const float4*)&A[(size_t)(row0 + arow) * KDIM + k0 + acol4];
        As[acol4 + 0][arow] = av.x;
        As[acol4 + 1][arow] = av.y;
        As[acol4 + 2][arow] = av.z;
        As[acol4 + 3][arow] = av.w;
        float4 bv = *(const float4*)&B[(size_t)(k0 + brow) * Ncols + col0 + bcol4];
        *(float4*)&Bs[brow][bcol4] = bv;
        __syncthreads();
#pragma unroll
        for (int k = 0; k < 16; k++) {
            float a[4], b[4];
#pragma unroll
            for (int i = 0; i < 4; i++) a[i] = As[k][ty * 4 + i];
#pragma unroll
            for (int j = 0; j < 4; j++) b[j] = Bs[k][tx * 4 + j];
#pragma unroll
            for (int i = 0; i < 4; i++)
#pragma unroll
                for (int j = 0; j < 4; j++) acc[i][j] = fmaf(a[i], b[j], acc[i][j]);
        }
        __syncthreads();
    }
#pragma unroll
    for (int i = 0; i < 4; i++) {
        int r = row0 + ty * 4 + i;
        if (r < M) {
            float4 v = make_float4(acc[i][0], acc[i][1], acc[i][2], acc[i][3]);
            *(float4*)&C[(size_t)r * Ncols + col0 + tx * 4] = v;
        }
    }
}

// ---------------- per-node attention scores ----------------
__global__ void scores_kernel(const float* __restrict__ h, const float* __restrict__ att, int TC) {
    int gw = (blockIdx.x * blockDim.x + threadIdx.x) >> 5;
    int lane = threadIdx.x & 31;
    if (gw >= NN) return;
    const float* row = h + (size_t)gw * TC;
    float a = 0.f, b = 0.f;
    for (int i = lane; i < TC; i += 32) {
        float v = row[i];
        a = fmaf(v, att[i], a);
        b = fmaf(v, att[TC + i], b);
    }
#pragma unroll
    for (int o = 16; o; o >>= 1) {
        a += __shfl_down_sync(0xffffffffu, a, o);
        b += __shfl_down_sync(0xffffffffu, b, o);
    }
    if (lane == 0) {
        g_si[gw] = a;
        g_sj[gw] = b;
    }
}

// ---------------- per-edge alpha + skl ----------------
__global__ void alpha_kernel(int t, double* __restrict__ skl_slot) {
    __shared__ float s_red[32];
    int e = blockIdx.x * blockDim.x + threadIdx.x;
    float skl = 0.f;
    if (e < EE) {
        int d = g_cdst[t][e], s = g_csrc[t][e];
        float l = g_si[d] + g_sj[s];
        l = l > 0.f ? l : 0.2f * l;
        float p = 1.f / (1.f + expf(-l));
        p = fminf(fmaxf(p, 0.01f), 0.99f);
        g_alpha[e] = p * g_invdeg[t][d];
        float q = 1.0f / (1.0f + expf(-(1.0f / 15.0f)));
        skl = p * (logf(p) - logf(q)) + (1.f - p) * (logf(1.f - p) - logf(1.f - q));
    }
    float tot = blockReduceSum(skl, s_red);
    if (threadIdx.x == 0) atomicAdd(skl_slot, (double)tot);
}

// ---------------- aggregation + KL epilogue ----------------
template <int C>
__global__ void agg_kernel(const float* __restrict__ h, const float* __restrict__ alpha,
                           const int* __restrict__ csrc, const int* __restrict__ rowptr,
                           const float* __restrict__ bias, float* __restrict__ mu_out,
                           double* __restrict__ acc_slot) {
    constexpr int TC = 2 * C;
    __shared__ float s_alpha[TC];
    __shared__ int s_src[TC];
    __shared__ float s_std[C];
    __shared__ float s_red[32];
    int n = blockIdx.x, tid = threadIdx.x;
    int start = rowptr[n], end = rowptr[n + 1];
    float acc = 0.f;
    for (int base = start; base < end; base += TC) {
        int cnt = min(TC, end - base);
        if (tid < cnt) {
            s_alpha[tid] = alpha[base + tid];
            s_src[tid] = csrc[base + tid];
        }
        __syncthreads();
        for (int i = 0; i < cnt; i++)
            acc = fmaf(s_alpha[i], h[(size_t)s_src[i] * TC + tid], acc);
        __syncthreads();
    }
    acc += bias[tid];
    if (tid >= C) {
        float x = acc;
        float sp = fmaxf(x, 0.f) + log1pf(expf(-fabsf(x)));
        s_std[tid - C] = sp + 1e-10f;
    }
    __syncthreads();
    float kl = 0.f;
    if (tid < C) {
        float mu = acc, sd = s_std[tid];
        kl = -logf(sd) + 0.5f * fmaf(sd, sd, mu * mu) - 0.5f;
        mu_out[(size_t)n * C + tid] = mu;
    }
    float tot = blockReduceSum(kl, s_red);
    if (tid == 0) atomicAdd(acc_slot, (double)tot);
}

// ---------------- temporal fusion / activations ----------------
__global__ void fuse1_kernel() {
    int i = blockIdx.x * blockDim.x + threadIdx.x;
    if (i < NN * 128) {
        float m0 = g_mu0[i], m1 = g_mu1[i];
        g_mu1[i] = fmaxf(0.4f * m0 + 0.2f * m1, 0.f);  // h1[1] = relu(0.4*mu0 + 0.2*mu1)
        g_mu0[i] = fmaxf(m0, 0.f);                      // h1[0] = relu(mu0)
    }
}

__global__ void fuse2_kernel(float* __restrict__ out) {
    int i = blockIdx.x * blockDim.x + threadIdx.x;
    if (i < NN * 64) out[NN * 64 + i] = 0.4f * out[i] + 0.2f * g_mu1[i];
}

__global__ void finalize_kernel(float* __restrict__ out, int out_size) {
    double ixz = (g_acc[0] + g_acc[1] + g_acc[2] + g_acc[3]) / (4.0 * (double)NN);
    double skl = (g_acc[4] + g_acc[5] + g_acc[6] + g_acc[7]) / (4.0 * (double)EE);
    out[out_size - 2] = (float)ixz;
    out[out_size - 1] = (float)skl;
}

// ---------------- launch ----------------
extern "C" void kernel_launch(void* const* d_in, const int* in_sizes, int n_in,
                              void* d_out, int out_size) {
    const float* x_all = (const float*)d_in[0];   // [T, N, 128]
    const int* ei = (const int*)d_in[1];          // [T, 2, E]
    const float* W1 = (const float*)d_in[2];      // [128, 256]
    const float* att1 = (const float*)d_in[3];    // [512]
    const float* b1 = (const float*)d_in[4];      // [256]
    const float* W2 = (const float*)d_in[5];      // [128, 128]
    const float* att2 = (const float*)d_in[6];    // [256]
    const float* b2 = (const float*)d_in[7];      // [128]
    float* out = (float*)d_out;

    float *p_h, *p_mu0, *p_mu1, *p_alpha;
    int *p_csrc, *p_rowptr;
    double* p_acc;
    cudaGetSymbolAddress((void**)&p_h, g_h);
    cudaGetSymbolAddress((void**)&p_mu0, g_mu0);
    cudaGetSymbolAddress((void**)&p_mu1, g_mu1);
    cudaGetSymbolAddress((void**)&p_alpha, g_alpha);
    cudaGetSymbolAddress((void**)&p_csrc, g_csrc);
    cudaGetSymbolAddress((void**)&p_rowptr, g_rowptr);
    cudaGetSymbolAddress((void**)&p_acc, g_acc);

    const int EB = (EE + 255) / 256;

    zero_kernel<<<(TT * NN + 255) / 256, 256>>>();
    for (int t = 0; t < TT; t++) {
        const int* src = ei + (size_t)t * 2 * EE;
        const int* dst = src + EE;
        hist_kernel<<<EB, 256>>>(dst, t);
        scan_kernel<<<1, 1024>>>(t);
        scatter_kernel<<<EB, 256>>>(src, dst, t);
    }

    // -------- layer 1 (C = 128) --------
    for (int t = 0; t < TT; t++) {
        gemm_kernel<<<dim3(256 / 64, (NN + 63) / 64), 256>>>(x_all + (size_t)t * NN * KDIM, W1, p_h, NN, 256);
        scores_kernel<<<(NN * 32 + 255) / 256, 256>>>(p_h, att1, 256);
        alpha_kernel<<<EB, 256>>>(t, p_acc + 4 + t);
        agg_kernel<128><<<NN, 256>>>(p_h, p_alpha, p_csrc + (size_t)t * EE,
                                     p_rowptr + (size_t)t * (NN + 1), b1,
                                     t ? p_mu1 : p_mu0, p_acc + t);
    }
    fuse1_kernel<<<(NN * 128 + 255) / 256, 256>>>();

    // -------- layer 2 (C = 64) --------
    for (int t = 0; t < TT; t++) {
        const float* xin = t ? p_mu1 : p_mu0;
        gemm_kernel<<<dim3(128 / 64, (NN + 63) / 64), 256>>>(xin, W2, p_h, NN, 128);
        scores_kernel<<<(NN * 32 + 255) / 256, 256>>>(p_h, att2, 128);
        alpha_kernel<<<EB, 256>>>(t, p_acc + 6 + t);
        agg_kernel<64><<<NN, 128>>>(p_h, p_alpha, p_csrc + (size_t)t * EE,
                                    p_rowptr + (size_t)t * (NN + 1), b2,
                                    t ? p_mu1 : out, p_acc + 2 + t);
    }
    fuse2_kernel<<<(NN * 64 + 255) / 256, 256>>>(out);
    finalize_kernel<<<1, 1>>>(out, out_size);
}